// round 13
// baseline (speedup 1.0000x reference)
#include <cuda_runtime.h>
#include <math.h>

// ---------------------------------------------------------------------------
// FCOS post-processing, ONE fused kernel.
//   Each block decodes a chunk of one batch (scores+classes, push >= T0).
//   The LAST block to finish a batch (threadfence + done-counter) runs that
//   batch's NMS immediately: histogram-prune to top-K prefix (~220) ->
//   global rank sort -> per-class warp greedy -> ballot-scan survivor ranks.
// Exactness: bin-thresholded candidate sets are complete score-prefixes of the
// global ranking; greedy suppression is intra-class and flows down-rank, so if
// >=100 prefix candidates survive NMS they are exactly the reference's first
// 100 picks (verified at runtime; widen, then exact full fallback otherwise).
// ---------------------------------------------------------------------------

#define BATCH   16
#define NCLS    80
#define NTOT    17064          // 12800 + 3200 + 800 + 208 + 56
#define NGROUP  (NTOT / 4)     // 4266
#define POSTK   100
#define CAP     4096           // gmem candidate list capacity
#define KCAP    768            // smem working-set capacity
#define CLSCAP  64
#define NBIN    512
#define NT      512
#define BLKS    9              // ceil(NGROUP / NT)
#define T0      0.88f
#define TK1     192            // attempt-0 prefix target
#define KCAP1   512            // attempt-0 prefix cap (bump threshold above)

__device__ float         g_score[BATCH * NTOT];
__device__ unsigned char g_cls  [BATCH * NTOT];
__device__ int           g_cnt  [BATCH];          // zero-init at load
__device__ int           g_done [BATCH];          // zero-init at load
__device__ float         g_cand_s[BATCH * CAP];
__device__ int           g_cand_i[BATCH * CAP];   // anchor | (cls<<16)

struct LevelPtrs {
    const float* cls[5];
    const float* box[5];
    const float* ctr[5];
};

__constant__ int   c_off[6]    = {0, 12800, 16000, 16800, 17008, 17064};
__constant__ int   c_W[5]      = {128, 64, 32, 16, 8};
__constant__ float c_stride[5] = {8.f, 16.f, 32.f, 64.f, 128.f};

__device__ __forceinline__ float sigmoidf_(float x) {
    return 1.0f / (1.0f + expf(-x));
}
__device__ __forceinline__ float iou_(const float4 a, const float4 b) {
    float ix1 = fmaxf(a.x, b.x), iy1 = fmaxf(a.y, b.y);
    float ix2 = fminf(a.z, b.z), iy2 = fminf(a.w, b.w);
    float inter = fmaxf(ix2 - ix1, 0.f) * fmaxf(iy2 - iy1, 0.f);
    float aa = (a.z - a.x) * (a.w - a.y);
    float ab = (b.z - b.x) * (b.w - b.y);
    return inter / (aa + ab - inter + 1e-9f);
}
__device__ __forceinline__ float4 decode_box(const LevelPtrs& p, int b, int a) {
    int lvl = (a >= 12800) + (a >= 16000) + (a >= 16800) + (a >= 17008);
    int   hw     = a - c_off[lvl];
    int   HW     = c_off[lvl + 1] - c_off[lvl];
    int   W      = c_W[lvl];
    float stride = c_stride[lvl];
    const float* bp = p.box[lvl] + (size_t)b * 4 * HW + hw;
    float l  = bp[0]      * stride;
    float t  = bp[HW]     * stride;
    float r  = bp[2 * HW] * stride;
    float d  = bp[3 * HW] * stride;
    float px = (hw % W) * stride + 0.5f * stride;
    float py = (hw / W) * stride + 0.5f * stride;
    return make_float4(fminf(fmaxf(px - l, 0.f), 1023.f),
                       fminf(fmaxf(py - t, 0.f), 799.f),
                       fminf(fmaxf(px + r, 0.f), 1023.f),
                       fminf(fmaxf(py + d, 0.f), 799.f));
}

// ---------------------------------------------------------------------------
extern __shared__ char smemn[];

__global__ void __launch_bounds__(NT) fused_kernel(LevelPtrs p,
                                                   float* __restrict__ out) {
    const int b    = blockIdx.y;
    const int tid  = threadIdx.x;
    const int warp = tid >> 5;
    const int lane = tid & 31;
    const int nwarps = NT / 32;

    __shared__ int s_last;

    // ======================= DECODE PHASE ==================================
    {
        int g = blockIdx.x * NT + tid;
        if (g < NGROUP) {
            int a0 = g * 4;
            int lvl = (a0 >= 12800) + (a0 >= 16000) + (a0 >= 16800) + (a0 >= 17008);
            int hw0 = a0 - c_off[lvl];
            int HW  = c_off[lvl + 1] - c_off[lvl];
            int HW4 = HW >> 2;

            const float4* __restrict__ cp = reinterpret_cast<const float4*>(
                p.cls[lvl] + (size_t)b * NCLS * HW + hw0);
            float4 best = cp[0];
            int4   bi   = make_int4(0, 0, 0, 0);
#pragma unroll 8
            for (int c = 1; c < NCLS; c++) {
                float4 v = cp[(size_t)c * HW4];
                if (v.x > best.x) { best.x = v.x; bi.x = c; }
                if (v.y > best.y) { best.y = v.y; bi.y = c; }
                if (v.z > best.z) { best.z = v.z; bi.z = c; }
                if (v.w > best.w) { best.w = v.w; bi.w = c; }
            }

            float4 ct = *reinterpret_cast<const float4*>(
                p.ctr[lvl] + (size_t)b * HW + hw0);

            float4 s4;
            s4.x = sqrtf(sigmoidf_(best.x) * sigmoidf_(ct.x));
            s4.y = sqrtf(sigmoidf_(best.y) * sigmoidf_(ct.y));
            s4.z = sqrtf(sigmoidf_(best.z) * sigmoidf_(ct.z));
            s4.w = sqrtf(sigmoidf_(best.w) * sigmoidf_(ct.w));

            int gi = b * NTOT + a0;
            reinterpret_cast<float4*>(g_score)[gi >> 2] = s4;
            *reinterpret_cast<uchar4*>(&g_cls[gi]) =
                make_uchar4((unsigned char)bi.x, (unsigned char)bi.y,
                            (unsigned char)bi.z, (unsigned char)bi.w);

            float sA[4] = {s4.x, s4.y, s4.z, s4.w};
            int   cA[4] = {bi.x, bi.y, bi.z, bi.w};
#pragma unroll
            for (int j = 0; j < 4; j++) {
                if (sA[j] >= T0) {
                    int pos = atomicAdd(&g_cnt[b], 1);
                    if (pos < CAP) {
                        g_cand_s[b * CAP + pos] = sA[j];
                        g_cand_i[b * CAP + pos] = (a0 + j) | (cA[j] << 16);
                    }
                }
            }
        }
    }

    // ======================= LAST-BLOCK HANDOFF ============================
    __syncthreads();
    if (tid == 0) {
        __threadfence();
        int old = atomicAdd(&g_done[b], 1);
        s_last = (old == BLKS - 1);
    }
    __syncthreads();
    if (!s_last) return;

    // ======================= NMS PHASE (last block of batch b) =============
    float4*         wbox     = (float4*)smemn;                         // 12288
    float*          ts       = (float*)(smemn + KCAP * 16);            // 3072
    int*            tp       = (int*)((char*)ts + KCAP * 4);           // 3072
    float*          ws       = (float*)((char*)tp + KCAP * 4);         // 3072
    int*            wi       = (int*)((char*)ws + KCAP * 4);           // 3072
    unsigned char*  wc       = (unsigned char*)((char*)wi + KCAP * 4); // 768
    unsigned char*  wkeep    = wc + KCAP;                              // 768
    unsigned short* cls_list = (unsigned short*)(wkeep + KCAP);        // 10240
    int*            hist     = (int*)((char*)cls_list + NCLS * CLSCAP * 2); // 2048

    __shared__ int s_part[32];
    __shared__ int s_chunk[32];
    __shared__ int s_ccnt[NCLS];
    __shared__ int s_total, s_t, s_K, s_ovf, s_S;
    __shared__ float  s_bv[32];
    __shared__ int    s_bi[32];
    __shared__ float4 s_pbox;
    __shared__ int    s_pcls;
    __shared__ float  s_pval;

    if (tid == 0) {
        s_total   = g_cnt[b];   // fence-ordered by done-counter protocol
        g_cnt[b]  = 0;          // reset for next graph replay
        g_done[b] = 0;
    }
    __syncthreads();
    const int total = s_total;
    const int C     = min(total, CAP);

    bool need_fallback = (total > CAP);
    int  wrote = 0;
    const float binscale = (float)NBIN / (1.0f - T0);

    if (!need_fallback) {
        // ---- histogram of candidate scores over [T0, 1) -------------------
        hist[tid] = 0;
        __syncthreads();
        for (int i = tid; i < C; i += NT) {
            float s = g_cand_s[b * CAP + i];
            int bin = min(NBIN - 1, max(0, (int)((s - T0) * binscale)));
            atomicAdd(&hist[bin], 1);
        }
        __syncthreads();
        // ---- suffix sum (warp shuffles); hist[t] := #scores in bins >= t --
        {
            int val = hist[tid];
#pragma unroll
            for (int off = 1; off < 32; off <<= 1) {
                int v = __shfl_down_sync(0xffffffffu, val, off);
                if (lane + off < 32) val += v;
            }
            if (lane == 0) s_part[warp] = val;
            __syncthreads();
            if (warp == 0) {
                int pv = (lane < nwarps) ? s_part[lane] : 0;
#pragma unroll
                for (int off = 1; off < 32; off <<= 1) {
                    int v = __shfl_down_sync(0xffffffffu, pv, off);
                    if (lane + off < 32) pv += v;
                }
                int excl = __shfl_down_sync(0xffffffffu, pv, 1);
                if (lane == 31) excl = 0;
                s_part[lane] = excl;
            }
            __syncthreads();
            hist[tid] = val + s_part[warp];
            __syncthreads();
        }

        for (int attempt = 0; attempt < 2 && !wrote && !need_fallback; attempt++) {
            if (tid == 0) { s_t = 0; s_K = 0; s_ovf = 0; }
            __syncthreads();
            if (attempt == 0) {
                if (hist[tid] >= TK1 && (tid == NBIN - 1 || hist[tid + 1] < TK1))
                    s_t = tid;
            }
            __syncthreads();
            int t = s_t;
            if (attempt == 0 && t < NBIN - 1 && hist[t] > KCAP1) t = t + 1;

            // ---- compact prefix candidates into working set ---------------
            for (int i = tid; i < C; i += NT) {
                float s = g_cand_s[b * CAP + i];
                int bin = min(NBIN - 1, max(0, (int)((s - T0) * binscale)));
                if (bin >= t) {
                    int pos = atomicAdd(&s_K, 1);
                    if (pos < KCAP) {
                        ts[pos] = s;
                        tp[pos] = g_cand_i[b * CAP + i];
                    }
                }
            }
            __syncthreads();
            if (s_K > KCAP) { need_fallback = true; break; }  // not a prefix
            int K = s_K;

            // ---- global rank sort (score desc, anchor idx asc) ------------
            for (int i = tid; i < K; i += NT) {
                float si  = ts[i];
                int   pki = tp[i];
                int   ai  = pki & 0xFFFF;
                int   r   = 0;
                for (int j = 0; j < K; j++) {
                    float sj = ts[j];
                    r += (sj > si) || (sj == si && (tp[j] & 0xFFFF) < ai);
                }
                ws[r]    = si;
                wi[r]    = ai;
                wc[r]    = (unsigned char)(pki >> 16);
                wbox[r]  = decode_box(p, b, ai);
                wkeep[r] = 1;
            }
            __syncthreads();

            // ---- per-class compaction (sorted order preserved) ------------
            for (int c = warp; c < NCLS; c += nwarps) {
                int m = 0;
                for (int base = 0; base < K; base += 32) {
                    int  i  = base + lane;
                    bool pr = (i < K) && (wc[i] == (unsigned char)c);
                    unsigned mask = __ballot_sync(0xffffffffu, pr);
                    if (pr) {
                        int pos = m + __popc(mask & ((1u << lane) - 1));
                        if (pos < CLSCAP)
                            cls_list[c * CLSCAP + pos] = (unsigned short)i;
                    }
                    m += __popc(mask);
                }
                if (lane == 0) {
                    s_ccnt[c] = m;
                    if (m > CLSCAP) atomicExch(&s_ovf, 1);
                }
            }
            __syncthreads();
            if (s_ovf) { need_fallback = true; break; }

            // ---- per-class greedy (order already sorted) ------------------
            for (int c = warp; c < NCLS; c += nwarps) {
                int m = s_ccnt[c];
                const unsigned short* L = cls_list + c * CLSCAP;
                for (int r = 0; r < m; r++) {
                    int ir = L[r];
                    if (wkeep[ir]) {
                        float4 pb = wbox[ir];
                        for (int j = r + 1 + lane; j < m; j += 32) {
                            int ij = L[j];
                            if (wkeep[ij] && iou_(pb, wbox[ij]) > 0.6f)
                                wkeep[ij] = 0;
                        }
                    }
                    __syncwarp();
                }
            }
            __syncthreads();

            // ---- survivor ranks via ballot + chunk prefix scan ------------
            int nchunk = (K + 31) / 32;          // <= 24 (K <= KCAP1+slack)
            for (int chunk = warp; chunk < nchunk; chunk += nwarps) {
                int  i  = chunk * 32 + lane;
                bool kp = (i < K) && wkeep[i];
                unsigned mask = __ballot_sync(0xffffffffu, kp);
                if (lane == 0) s_chunk[chunk] = __popc(mask);
            }
            __syncthreads();
            if (warp == 0) {
                int v = (lane < nchunk) ? s_chunk[lane] : 0;
                int incl = v;
#pragma unroll
                for (int off = 1; off < 32; off <<= 1) {
                    int x = __shfl_up_sync(0xffffffffu, incl, off);
                    if (lane >= off) incl += x;
                }
                if (lane < nchunk) s_chunk[lane] = incl - v;   // exclusive
                if (lane == 31) s_S = incl;                    // total
            }
            __syncthreads();
            int S = s_S;

            if (S >= POSTK) {
                for (int chunk = warp; chunk < nchunk; chunk += nwarps) {
                    int  i  = chunk * 32 + lane;
                    bool kp = (i < K) && wkeep[i];
                    unsigned mask = __ballot_sync(0xffffffffu, kp);
                    if (kp) {
                        int r = s_chunk[chunk] + __popc(mask & ((1u << lane) - 1));
                        if (r < POSTK) {
                            float4 bb  = wbox[i];
                            float* det = out + ((size_t)b * POSTK + r) * 5;
                            det[0] = bb.x; det[1] = bb.y;
                            det[2] = bb.z; det[3] = bb.w;
                            det[4] = ws[i];
                            out[(size_t)BATCH * POSTK * 5 + b * POSTK + r] =
                                (float)wc[i];
                        }
                    }
                }
                wrote = 1;
            }
            __syncthreads();
        }
        if (!wrote) need_fallback = true;  // <100 survivors even with all >=T0
    }

    if (wrote) return;

    // ---- fallback: exact block-serial greedy over all anchors -------------
    // (statistically unreachable; g_score is replay-rewritten scratch.
    //  NOTE: reads only batch b's g_score, written by this batch's blocks,
    //  all complete per the done-counter protocol.)
    {
        float* gsm = g_score + b * NTOT;
        int written = 0;
        for (int k = 0; k < POSTK; k++) {
            float bv = -1e30f; int bix = 0x7fffffff;
            for (int i = tid; i < NTOT; i += NT) {
                float s = gsm[i];
                if (s > bv || (s == bv && i < bix)) { bv = s; bix = i; }
            }
#pragma unroll
            for (int off = 16; off; off >>= 1) {
                float ov = __shfl_down_sync(0xffffffffu, bv, off);
                int   oi = __shfl_down_sync(0xffffffffu, bix, off);
                if (ov > bv || (ov == bv && oi < bix)) { bv = ov; bix = oi; }
            }
            if (lane == 0) { s_bv[warp] = bv; s_bi[warp] = bix; }
            __syncthreads();
            if (tid == 0) {
                float fv = -1e30f; int fi = 0x7fffffff;
                for (int w2 = 0; w2 < nwarps; w2++) {
                    float cv = s_bv[w2]; int ci = s_bi[w2];
                    if (cv > fv || (cv == fv && ci < fi)) { fv = cv; fi = ci; }
                }
                s_pval = fv;
                if (fv > -1e29f) {
                    float4 pb = decode_box(p, b, fi);
                    s_pbox = pb;
                    s_pcls = g_cls[b * NTOT + fi];
                    float* det = out + ((size_t)b * POSTK + k) * 5;
                    det[0] = pb.x; det[1] = pb.y; det[2] = pb.z; det[3] = pb.w;
                    det[4] = fv;
                    out[(size_t)BATCH * POSTK * 5 + b * POSTK + k] =
                        (float)s_pcls;
                    gsm[fi] = -1e30f;
                }
            }
            __syncthreads();
            if (s_pval <= -1e29f) break;
            written++;
            float4 pb = s_pbox;
            int    pc = s_pcls;
            for (int i = tid; i < NTOT; i += NT) {
                float s = gsm[i];
                if (s > -1e29f && g_cls[b * NTOT + i] == pc) {
                    if (iou_(pb, decode_box(p, b, i)) > 0.6f) gsm[i] = -1e30f;
                }
            }
            __syncthreads();
        }
        for (int k = written + tid; k < POSTK; k += NT) {
            float* det = out + ((size_t)b * POSTK + k) * 5;
            det[0] = 0.f; det[1] = 0.f; det[2] = 0.f; det[3] = 0.f; det[4] = -1.f;
            out[(size_t)BATCH * POSTK * 5 + b * POSTK + k] = -1.f;
        }
    }
}

// ---------------------------------------------------------------------------
extern "C" void kernel_launch(void* const* d_in, const int* in_sizes, int n_in,
                              void* d_out, int out_size) {
    (void)n_in; (void)out_size;

    LevelPtrs p;
    if (in_sizes[1] == 819200) {
        for (int i = 0; i < 5; i++) {          // interleaved (cls,box,ctr)/level
            p.cls[i] = (const float*)d_in[3 * i + 0];
            p.box[i] = (const float*)d_in[3 * i + 1];
            p.ctr[i] = (const float*)d_in[3 * i + 2];
        }
    } else {
        for (int i = 0; i < 5; i++) {          // planar cls x5, box x5, ctr x5
            p.cls[i] = (const float*)d_in[i];
            p.box[i] = (const float*)d_in[5 + i];
            p.ctr[i] = (const float*)d_in[10 + i];
        }
    }

    const int smem_bytes = KCAP * 16 + 4 * KCAP * 4 + 2 * KCAP
                         + NCLS * CLSCAP * 2 + NBIN * 4;   // 38,400 B
    cudaFuncSetAttribute(fused_kernel,
                         cudaFuncAttributeMaxDynamicSharedMemorySize, smem_bytes);

    dim3 grid(BLKS, BATCH);   // 9 x 16 = 144 blocks
    fused_kernel<<<grid, NT, smem_bytes>>>(p, (float*)d_out);
}

// round 14
// speedup vs baseline: 1.1207x; 1.1207x over previous
#include <cuda_runtime.h>
#include <math.h>

// ---------------------------------------------------------------------------
// FCOS post-processing, 2 kernels.
//   decode (grid-wide, 2 threads/anchor-group): scores+classes; pushes
//       candidates with score >= T0 WITH precomputed boxes.
//   nms (block/batch): single smem sweep -> histogram-prune to top-K prefix
//       (~220) -> rank sort -> per-class warp greedy -> ballot-scan ranks.
// Exactness: bin-thresholded candidate sets are complete score-prefixes of the
// global ranking; greedy suppression is intra-class and flows down-rank, so if
// >=100 prefix candidates survive NMS they are exactly the reference's first
// 100 picks (verified at runtime; widen, then exact full fallback otherwise).
// ---------------------------------------------------------------------------

#define BATCH   16
#define NCLS    80
#define NTOT    17064          // 12800 + 3200 + 800 + 208 + 56
#define NGROUP  (NTOT / 4)     // 4266
#define POSTK   100
#define CAP     4096           // gmem candidate list capacity
#define KCAP    768            // pruned working-set capacity
#define CLSCAP  64
#define NBIN    1024
#define NTN     1024
#define T0      0.88f
#define TK1     192            // attempt-0 prefix target
#define KCAP1   512            // attempt-0 prefix cap (bump threshold above)

__device__ float         g_score[BATCH * NTOT];     // for fallback only
__device__ unsigned char g_cls  [BATCH * NTOT];     // for fallback only
__device__ int           g_cnt  [BATCH];            // zero-init at load
__device__ float         g_cand_s  [BATCH * CAP];
__device__ int           g_cand_i  [BATCH * CAP];   // anchor | (cls<<16)
__device__ float4        g_cand_box[BATCH * CAP];

struct LevelPtrs {
    const float* cls[5];
    const float* box[5];
    const float* ctr[5];
};

__constant__ int   c_off[6]    = {0, 12800, 16000, 16800, 17008, 17064};
__constant__ int   c_W[5]      = {128, 64, 32, 16, 8};
__constant__ float c_stride[5] = {8.f, 16.f, 32.f, 64.f, 128.f};

__device__ __forceinline__ float sigmoidf_(float x) {
    return 1.0f / (1.0f + expf(-x));
}
__device__ __forceinline__ float iou_(const float4 a, const float4 b) {
    float ix1 = fmaxf(a.x, b.x), iy1 = fmaxf(a.y, b.y);
    float ix2 = fminf(a.z, b.z), iy2 = fminf(a.w, b.w);
    float inter = fmaxf(ix2 - ix1, 0.f) * fmaxf(iy2 - iy1, 0.f);
    float aa = (a.z - a.x) * (a.w - a.y);
    float ab = (b.z - b.x) * (b.w - b.y);
    return inter / (aa + ab - inter + 1e-9f);
}
__device__ __forceinline__ float4 decode_box(const LevelPtrs& p, int b, int a) {
    int lvl = (a >= 12800) + (a >= 16000) + (a >= 16800) + (a >= 17008);
    int   hw     = a - c_off[lvl];
    int   HW     = c_off[lvl + 1] - c_off[lvl];
    int   W      = c_W[lvl];
    float stride = c_stride[lvl];
    const float* bp = p.box[lvl] + (size_t)b * 4 * HW + hw;
    float l  = bp[0]      * stride;
    float t  = bp[HW]     * stride;
    float r  = bp[2 * HW] * stride;
    float d  = bp[3 * HW] * stride;
    float px = (hw % W) * stride + 0.5f * stride;
    float py = (hw / W) * stride + 0.5f * stride;
    return make_float4(fminf(fmaxf(px - l, 0.f), 1023.f),
                       fminf(fmaxf(py - t, 0.f), 799.f),
                       fminf(fmaxf(px + r, 0.f), 1023.f),
                       fminf(fmaxf(py + d, 0.f), 799.f));
}

// ---------------------------------------------------------------------------
// Decode: 2 threads per 4-anchor group (40 classes each, shfl-combined).
// ---------------------------------------------------------------------------
__global__ void decode_kernel(LevelPtrs p) {
    int gid = blockIdx.x * blockDim.x + threadIdx.x;   // over NGROUP*2
    int b   = blockIdx.y;
    int greal = gid >> 1;
    int h     = gid & 1;                               // class half
    int g     = min(greal, NGROUP - 1);                // clamp: full-warp shfl
    int a0    = g * 4;

    int lvl = (a0 >= 12800) + (a0 >= 16000) + (a0 >= 16800) + (a0 >= 17008);
    int hw0 = a0 - c_off[lvl];
    int HW  = c_off[lvl + 1] - c_off[lvl];
    int HW4 = HW >> 2;

    const float4* __restrict__ cp = reinterpret_cast<const float4*>(
        p.cls[lvl] + (size_t)b * NCLS * HW + hw0) + (size_t)(h * 40) * HW4;
    float4 best = cp[0];
    int4   bi   = make_int4(h * 40, h * 40, h * 40, h * 40);
#pragma unroll 8
    for (int c = 1; c < 40; c++) {
        float4 v = cp[(size_t)c * HW4];
        if (v.x > best.x) { best.x = v.x; bi.x = h * 40 + c; }
        if (v.y > best.y) { best.y = v.y; bi.y = h * 40 + c; }
        if (v.z > best.z) { best.z = v.z; bi.z = h * 40 + c; }
        if (v.w > best.w) { best.w = v.w; bi.w = h * 40 + c; }
    }

    // combine halves: (value desc, class idx asc) == argmax-first semantics
    float bv[4] = {best.x, best.y, best.z, best.w};
    int   bc[4] = {bi.x, bi.y, bi.z, bi.w};
#pragma unroll
    for (int j = 0; j < 4; j++) {
        float ov = __shfl_xor_sync(0xffffffffu, bv[j], 1);
        int   oi = __shfl_xor_sync(0xffffffffu, bc[j], 1);
        if (ov > bv[j] || (ov == bv[j] && oi < bc[j])) { bv[j] = ov; bc[j] = oi; }
    }
    if (h || greal >= NGROUP) return;

    float4 ct = *reinterpret_cast<const float4*>(p.ctr[lvl] + (size_t)b * HW + hw0);
    float cv[4] = {ct.x, ct.y, ct.z, ct.w};

    float4 s4;
    float* s4p = &s4.x;
#pragma unroll
    for (int j = 0; j < 4; j++)
        s4p[j] = sqrtf(sigmoidf_(bv[j]) * sigmoidf_(cv[j]));

    int gi = b * NTOT + a0;
    reinterpret_cast<float4*>(g_score)[gi >> 2] = s4;
    *reinterpret_cast<uchar4*>(&g_cls[gi]) =
        make_uchar4((unsigned char)bc[0], (unsigned char)bc[1],
                    (unsigned char)bc[2], (unsigned char)bc[3]);

#pragma unroll
    for (int j = 0; j < 4; j++) {
        if (s4p[j] >= T0) {
            int pos = atomicAdd(&g_cnt[b], 1);
            if (pos < CAP) {
                g_cand_s[b * CAP + pos]   = s4p[j];
                g_cand_i[b * CAP + pos]   = (a0 + j) | (bc[j] << 16);
                g_cand_box[b * CAP + pos] = decode_box(p, b, a0 + j);
            }
        }
    }
}

// ---------------------------------------------------------------------------
// NMS: one block (1024 threads) per batch.
// ---------------------------------------------------------------------------
extern __shared__ char smemn[];

__global__ void __launch_bounds__(NTN, 1) nms_kernel(LevelPtrs p,
                                                     float* __restrict__ out) {
    float*          ts       = (float*)smemn;                          // 16K (all C scores)
    int*            tp       = (int*)(smemn + CAP * 4);                // 16K (all C packed)
    int*            hist     = (int*)((char*)tp + CAP * 4);            // 4K
    float*          cs       = (float*)((char*)hist + NBIN * 4);       // 3K (compacted)
    int*            cpk      = (int*)((char*)cs + KCAP * 4);           // 3K
    int*            cslot    = (int*)((char*)cpk + KCAP * 4);          // 3K
    float4*         wbox     = (float4*)((char*)cslot + KCAP * 4);     // 12K (sorted)
    float*          ws       = (float*)((char*)wbox + KCAP * 16);      // 3K
    int*            wi       = (int*)((char*)ws + KCAP * 4);           // 3K
    unsigned char*  wc       = (unsigned char*)((char*)wi + KCAP * 4); // .75K
    unsigned char*  wkeep    = wc + KCAP;                              // .75K
    unsigned short* cls_list = (unsigned short*)(wkeep + KCAP);        // 10K

    __shared__ int s_part[32];
    __shared__ int s_chunk[32];
    __shared__ int s_ccnt[NCLS];
    __shared__ int s_t, s_K, s_ovf, s_S;
    __shared__ float  s_bv[32];
    __shared__ int    s_bi[32];
    __shared__ float4 s_pbox;
    __shared__ int    s_pcls;
    __shared__ float  s_pval;

    const int b    = blockIdx.x;
    const int tid  = threadIdx.x;
    const int warp = tid >> 5;
    const int lane = tid & 31;

    const int total = g_cnt[b];
    const int C     = min(total, CAP);
    if (tid == 0) g_cnt[b] = 0;          // reset for next graph replay

    bool need_fallback = (total > CAP);
    int  wrote = 0;
    const float binscale = (float)NBIN / (1.0f - T0);

    if (!need_fallback) {
        // ---- ONE gmem sweep: load candidates to smem + histogram ----------
        hist[tid] = 0;
        __syncthreads();
        for (int i = tid; i < C; i += NTN) {
            float s = g_cand_s[b * CAP + i];
            ts[i] = s;
            tp[i] = g_cand_i[b * CAP + i];
            int bin = min(NBIN - 1, max(0, (int)((s - T0) * binscale)));
            atomicAdd(&hist[bin], 1);
        }
        __syncthreads();
        // ---- suffix sum (warp shuffles); hist[t] := #scores in bins >= t --
        {
            int val = hist[tid];
#pragma unroll
            for (int off = 1; off < 32; off <<= 1) {
                int v = __shfl_down_sync(0xffffffffu, val, off);
                if (lane + off < 32) val += v;
            }
            if (lane == 0) s_part[warp] = val;
            __syncthreads();
            if (warp == 0) {
                int pv = s_part[lane];
#pragma unroll
                for (int off = 1; off < 32; off <<= 1) {
                    int v = __shfl_down_sync(0xffffffffu, pv, off);
                    if (lane + off < 32) pv += v;
                }
                int excl = __shfl_down_sync(0xffffffffu, pv, 1);
                if (lane == 31) excl = 0;
                s_part[lane] = excl;
            }
            __syncthreads();
            hist[tid] = val + s_part[warp];
            __syncthreads();
        }

        for (int attempt = 0; attempt < 2 && !wrote && !need_fallback; attempt++) {
            if (tid == 0) { s_t = 0; s_K = 0; s_ovf = 0; }
            __syncthreads();
            if (attempt == 0) {
                if (hist[tid] >= TK1 && (tid == NBIN - 1 || hist[tid + 1] < TK1))
                    s_t = tid;
            }
            __syncthreads();
            int t = s_t;
            if (attempt == 0 && t < NBIN - 1 && hist[t] > KCAP1) t = t + 1;

            // ---- compact prefix candidates (smem -> smem) -----------------
            for (int i = tid; i < C; i += NTN) {
                float s = ts[i];
                int bin = min(NBIN - 1, max(0, (int)((s - T0) * binscale)));
                if (bin >= t) {
                    int pos = atomicAdd(&s_K, 1);
                    if (pos < KCAP) {
                        cs[pos]    = s;
                        cpk[pos]   = tp[i];
                        cslot[pos] = i;
                    }
                }
            }
            __syncthreads();
            if (s_K > KCAP) { need_fallback = true; break; }
            int K = s_K;

            // ---- global rank sort (score desc, anchor idx asc) ------------
            for (int i = tid; i < K; i += NTN) {
                float si  = cs[i];
                int   pki = cpk[i];
                int   ai  = pki & 0xFFFF;
                int   r   = 0;
                for (int j = 0; j < K; j++) {
                    float sj = cs[j];
                    r += (sj > si) || (sj == si && (cpk[j] & 0xFFFF) < ai);
                }
                ws[r]    = si;
                wi[r]    = ai;
                wc[r]    = (unsigned char)(pki >> 16);
                wbox[r]  = g_cand_box[b * CAP + cslot[i]];
                wkeep[r] = 1;
            }
            __syncthreads();

            // ---- per-class compaction (sorted order preserved) ------------
            for (int c = warp; c < NCLS; c += 32) {
                int m = 0;
                for (int base = 0; base < K; base += 32) {
                    int  i  = base + lane;
                    bool pr = (i < K) && (wc[i] == (unsigned char)c);
                    unsigned mask = __ballot_sync(0xffffffffu, pr);
                    if (pr) {
                        int pos = m + __popc(mask & ((1u << lane) - 1));
                        if (pos < CLSCAP)
                            cls_list[c * CLSCAP + pos] = (unsigned short)i;
                    }
                    m += __popc(mask);
                }
                if (lane == 0) {
                    s_ccnt[c] = m;
                    if (m > CLSCAP) atomicExch(&s_ovf, 1);
                }
            }
            __syncthreads();
            if (s_ovf) { need_fallback = true; break; }

            // ---- per-class greedy (order already sorted) ------------------
            for (int c = warp; c < NCLS; c += 32) {
                int m = s_ccnt[c];
                const unsigned short* L = cls_list + c * CLSCAP;
                for (int r = 0; r < m; r++) {
                    int ir = L[r];
                    if (wkeep[ir]) {
                        float4 pb = wbox[ir];
                        for (int j = r + 1 + lane; j < m; j += 32) {
                            int ij = L[j];
                            if (wkeep[ij] && iou_(pb, wbox[ij]) > 0.6f)
                                wkeep[ij] = 0;
                        }
                    }
                    __syncwarp();
                }
            }
            __syncthreads();

            // ---- survivor ranks via ballot + chunk prefix scan ------------
            int nchunk = (K + 31) / 32;
            for (int chunk = warp; chunk < nchunk; chunk += 32) {
                int  i  = chunk * 32 + lane;
                bool kp = (i < K) && wkeep[i];
                unsigned mask = __ballot_sync(0xffffffffu, kp);
                if (lane == 0) s_chunk[chunk] = __popc(mask);
            }
            __syncthreads();
            if (warp == 0) {
                int v = (lane < nchunk) ? s_chunk[lane] : 0;
                int incl = v;
#pragma unroll
                for (int off = 1; off < 32; off <<= 1) {
                    int x = __shfl_up_sync(0xffffffffu, incl, off);
                    if (lane >= off) incl += x;
                }
                if (lane < nchunk) s_chunk[lane] = incl - v;   // exclusive
                if (lane == 31) s_S = incl;
            }
            __syncthreads();
            int S = s_S;

            if (S >= POSTK) {
                for (int chunk = warp; chunk < nchunk; chunk += 32) {
                    int  i  = chunk * 32 + lane;
                    bool kp = (i < K) && wkeep[i];
                    unsigned mask = __ballot_sync(0xffffffffu, kp);
                    if (kp) {
                        int r = s_chunk[chunk] + __popc(mask & ((1u << lane) - 1));
                        if (r < POSTK) {
                            float4 bb  = wbox[i];
                            float* det = out + ((size_t)b * POSTK + r) * 5;
                            det[0] = bb.x; det[1] = bb.y;
                            det[2] = bb.z; det[3] = bb.w;
                            det[4] = ws[i];
                            out[(size_t)BATCH * POSTK * 5 + b * POSTK + r] =
                                (float)wc[i];
                        }
                    }
                }
                wrote = 1;
            }
            __syncthreads();
        }
        if (!wrote) need_fallback = true;
    }

    if (wrote) return;

    // ---- fallback: exact block-serial greedy over all anchors -------------
    // (statistically unreachable; g_score is replay-rewritten scratch)
    {
        float* gsm = g_score + b * NTOT;
        int written = 0;
        for (int k = 0; k < POSTK; k++) {
            float bv = -1e30f; int bix = 0x7fffffff;
            for (int i = tid; i < NTOT; i += NTN) {
                float s = gsm[i];
                if (s > bv || (s == bv && i < bix)) { bv = s; bix = i; }
            }
#pragma unroll
            for (int off = 16; off; off >>= 1) {
                float ov = __shfl_down_sync(0xffffffffu, bv, off);
                int   oi = __shfl_down_sync(0xffffffffu, bix, off);
                if (ov > bv || (ov == bv && oi < bix)) { bv = ov; bix = oi; }
            }
            if (lane == 0) { s_bv[warp] = bv; s_bi[warp] = bix; }
            __syncthreads();
            if (tid == 0) {
                float fv = -1e30f; int fi = 0x7fffffff;
                for (int w2 = 0; w2 < 32; w2++) {
                    float cv = s_bv[w2]; int ci = s_bi[w2];
                    if (cv > fv || (cv == fv && ci < fi)) { fv = cv; fi = ci; }
                }
                s_pval = fv;
                if (fv > -1e29f) {
                    float4 pb = decode_box(p, b, fi);
                    s_pbox = pb;
                    s_pcls = g_cls[b * NTOT + fi];
                    float* det = out + ((size_t)b * POSTK + k) * 5;
                    det[0] = pb.x; det[1] = pb.y; det[2] = pb.z; det[3] = pb.w;
                    det[4] = fv;
                    out[(size_t)BATCH * POSTK * 5 + b * POSTK + k] =
                        (float)s_pcls;
                    gsm[fi] = -1e30f;
                }
            }
            __syncthreads();
            if (s_pval <= -1e29f) break;
            written++;
            float4 pb = s_pbox;
            int    pc = s_pcls;
            for (int i = tid; i < NTOT; i += NTN) {
                float s = gsm[i];
                if (s > -1e29f && g_cls[b * NTOT + i] == pc) {
                    if (iou_(pb, decode_box(p, b, i)) > 0.6f) gsm[i] = -1e30f;
                }
            }
            __syncthreads();
        }
        for (int k = written + tid; k < POSTK; k += NTN) {
            float* det = out + ((size_t)b * POSTK + k) * 5;
            det[0] = 0.f; det[1] = 0.f; det[2] = 0.f; det[3] = 0.f; det[4] = -1.f;
            out[(size_t)BATCH * POSTK * 5 + b * POSTK + k] = -1.f;
        }
    }
}

// ---------------------------------------------------------------------------
extern "C" void kernel_launch(void* const* d_in, const int* in_sizes, int n_in,
                              void* d_out, int out_size) {
    (void)n_in; (void)out_size;

    LevelPtrs p;
    if (in_sizes[1] == 819200) {
        for (int i = 0; i < 5; i++) {          // interleaved (cls,box,ctr)/level
            p.cls[i] = (const float*)d_in[3 * i + 0];
            p.box[i] = (const float*)d_in[3 * i + 1];
            p.ctr[i] = (const float*)d_in[3 * i + 2];
        }
    } else {
        for (int i = 0; i < 5; i++) {          // planar cls x5, box x5, ctr x5
            p.cls[i] = (const float*)d_in[i];
            p.box[i] = (const float*)d_in[5 + i];
            p.ctr[i] = (const float*)d_in[10 + i];
        }
    }

    const int smem_bytes = CAP * 4 * 2 + NBIN * 4 + KCAP * (4 + 4 + 4)
                         + KCAP * 16 + KCAP * 4 * 2 + KCAP * 2
                         + NCLS * CLSCAP * 2;   // 76,288 B
    cudaFuncSetAttribute(nms_kernel,
                         cudaFuncAttributeMaxDynamicSharedMemorySize, smem_bytes);

    dim3 dgrid((NGROUP * 2 + 255) / 256, BATCH);   // 34 x 16
    decode_kernel<<<dgrid, 256>>>(p);

    nms_kernel<<<BATCH, NTN, smem_bytes>>>(p, (float*)d_out);
}

// round 15
// speedup vs baseline: 1.4617x; 1.3042x over previous
#include <cuda_runtime.h>
#include <math.h>

// ---------------------------------------------------------------------------
// FCOS post-processing, 2 kernels (R12 structure, consolidated).
//   decode (grid-wide): scores+classes; pushes candidates with score >= T0.
//   nms (block/batch):  single smem sweep + histogram-prune to top-K prefix
//       (~200) -> distributed rank sort -> per-class warp greedy ->
//       ballot-scan survivor ranks.
// Exactness: bin-thresholded candidate sets are complete score-prefixes of the
// global ranking; greedy suppression is intra-class and flows down-rank, so if
// >=100 prefix candidates survive NMS they are exactly the reference's first
// 100 picks (verified at runtime; widen, then exact full fallback otherwise).
// ---------------------------------------------------------------------------

#define BATCH   16
#define NCLS    80
#define NTOT    17064          // 12800 + 3200 + 800 + 208 + 56
#define NGROUP  (NTOT / 4)     // 4266
#define POSTK   100
#define CAP     4096           // gmem candidate list capacity
#define KCAP    768            // pruned working-set capacity
#define CLSCAP  64
#define NBIN    1024
#define NTN     1024
#define T0      0.88f
#define TK1     192            // attempt-0 prefix target
#define KCAP1   512            // attempt-0 prefix cap (bump threshold above)

__device__ float         g_score[BATCH * NTOT];     // fallback only
__device__ unsigned char g_cls  [BATCH * NTOT];     // fallback only
__device__ int           g_cnt  [BATCH];            // zero-init at load
__device__ float         g_cand_s[BATCH * CAP];
__device__ int           g_cand_i[BATCH * CAP];     // anchor | (cls<<16)

struct LevelPtrs {
    const float* cls[5];
    const float* box[5];
    const float* ctr[5];
};

__constant__ int   c_off[6]    = {0, 12800, 16000, 16800, 17008, 17064};
__constant__ int   c_W[5]      = {128, 64, 32, 16, 8};
__constant__ float c_stride[5] = {8.f, 16.f, 32.f, 64.f, 128.f};

__device__ __forceinline__ float sigmoidf_(float x) {
    return 1.0f / (1.0f + expf(-x));
}
__device__ __forceinline__ float iou_(const float4 a, const float4 b) {
    float ix1 = fmaxf(a.x, b.x), iy1 = fmaxf(a.y, b.y);
    float ix2 = fminf(a.z, b.z), iy2 = fminf(a.w, b.w);
    float inter = fmaxf(ix2 - ix1, 0.f) * fmaxf(iy2 - iy1, 0.f);
    float aa = (a.z - a.x) * (a.w - a.y);
    float ab = (b.z - b.x) * (b.w - b.y);
    return inter / (aa + ab - inter + 1e-9f);
}
__device__ __forceinline__ float4 decode_box(const LevelPtrs& p, int b, int a) {
    int lvl = (a >= 12800) + (a >= 16000) + (a >= 16800) + (a >= 17008);
    int   hw     = a - c_off[lvl];
    int   HW     = c_off[lvl + 1] - c_off[lvl];
    int   W      = c_W[lvl];
    float stride = c_stride[lvl];
    const float* bp = p.box[lvl] + (size_t)b * 4 * HW + hw;
    float l  = bp[0]      * stride;
    float t  = bp[HW]     * stride;
    float r  = bp[2 * HW] * stride;
    float d  = bp[3 * HW] * stride;
    float px = (hw % W) * stride + 0.5f * stride;
    float py = (hw / W) * stride + 0.5f * stride;
    return make_float4(fminf(fmaxf(px - l, 0.f), 1023.f),
                       fminf(fmaxf(py - t, 0.f), 799.f),
                       fminf(fmaxf(px + r, 0.f), 1023.f),
                       fminf(fmaxf(py + d, 0.f), 799.f));
}

// ---------------------------------------------------------------------------
// Decode: scores + classes; push candidates >= T0. One thread per 4 anchors.
// (Byte-identical to the R12 version.)
// ---------------------------------------------------------------------------
__global__ void decode_kernel(LevelPtrs p) {
    int g = blockIdx.x * blockDim.x + threadIdx.x;
    int b = blockIdx.y;
    if (g >= NGROUP) return;
    int a0 = g * 4;

    int lvl = (a0 >= 12800) + (a0 >= 16000) + (a0 >= 16800) + (a0 >= 17008);
    int hw0 = a0 - c_off[lvl];
    int HW  = c_off[lvl + 1] - c_off[lvl];
    int HW4 = HW >> 2;

    const float4* __restrict__ cp = reinterpret_cast<const float4*>(
        p.cls[lvl] + (size_t)b * NCLS * HW + hw0);
    float4 best = cp[0];
    int4   bi   = make_int4(0, 0, 0, 0);
#pragma unroll 8
    for (int c = 1; c < NCLS; c++) {
        float4 v = cp[(size_t)c * HW4];
        if (v.x > best.x) { best.x = v.x; bi.x = c; }
        if (v.y > best.y) { best.y = v.y; bi.y = c; }
        if (v.z > best.z) { best.z = v.z; bi.z = c; }
        if (v.w > best.w) { best.w = v.w; bi.w = c; }
    }

    float4 ct = *reinterpret_cast<const float4*>(p.ctr[lvl] + (size_t)b * HW + hw0);

    float4 s4;
    s4.x = sqrtf(sigmoidf_(best.x) * sigmoidf_(ct.x));
    s4.y = sqrtf(sigmoidf_(best.y) * sigmoidf_(ct.y));
    s4.z = sqrtf(sigmoidf_(best.z) * sigmoidf_(ct.z));
    s4.w = sqrtf(sigmoidf_(best.w) * sigmoidf_(ct.w));

    int gi = b * NTOT + a0;
    reinterpret_cast<float4*>(g_score)[gi >> 2] = s4;
    *reinterpret_cast<uchar4*>(&g_cls[gi]) =
        make_uchar4((unsigned char)bi.x, (unsigned char)bi.y,
                    (unsigned char)bi.z, (unsigned char)bi.w);

    float sA[4] = {s4.x, s4.y, s4.z, s4.w};
    int   cA[4] = {bi.x, bi.y, bi.z, bi.w};
#pragma unroll
    for (int j = 0; j < 4; j++) {
        if (sA[j] >= T0) {
            int pos = atomicAdd(&g_cnt[b], 1);
            if (pos < CAP) {
                g_cand_s[b * CAP + pos] = sA[j];
                g_cand_i[b * CAP + pos] = (a0 + j) | (cA[j] << 16);
            }
        }
    }
}

// ---------------------------------------------------------------------------
// NMS: one block (1024 threads) per batch.
// ---------------------------------------------------------------------------
extern __shared__ char smemn[];

__global__ void __launch_bounds__(NTN, 1) nms_kernel(LevelPtrs p,
                                                     float* __restrict__ out) {
    float4*         wbox     = (float4*)smemn;                          // 12K (sorted)
    float*          ts       = (float*)(smemn + KCAP * 16);             // 16K (all C scores)
    int*            tp       = (int*)((char*)ts + CAP * 4);             // 16K (all C packed)
    int*            hist     = (int*)((char*)tp + CAP * 4);             // 4K
    float*          cs       = (float*)((char*)hist + NBIN * 4);        // 3K (compacted)
    int*            cpk      = (int*)((char*)cs + KCAP * 4);            // 3K
    int*            srank    = (int*)((char*)cpk + KCAP * 4);           // 3K
    float*          ws       = (float*)((char*)srank + KCAP * 4);       // 3K (sorted)
    int*            wi       = (int*)((char*)ws + KCAP * 4);            // 3K
    unsigned short* cls_list = (unsigned short*)((char*)wi + KCAP * 4); // 10K
    unsigned char*  wc       = (unsigned char*)((char*)cls_list
                                                + NCLS * CLSCAP * 2);   // .75K
    unsigned char*  wkeep    = wc + KCAP;                               // .75K

    __shared__ int s_part[32];
    __shared__ int s_chunk[32];
    __shared__ int s_ccnt[NCLS];
    __shared__ int s_t, s_K, s_ovf, s_S;
    __shared__ float  s_bv[32];
    __shared__ int    s_bi[32];
    __shared__ float4 s_pbox;
    __shared__ int    s_pcls;
    __shared__ float  s_pval;

    const int b    = blockIdx.x;
    const int tid  = threadIdx.x;
    const int warp = tid >> 5;
    const int lane = tid & 31;

    const int total = g_cnt[b];
    const int C     = min(total, CAP);
    if (tid == 0) g_cnt[b] = 0;          // reset for next graph replay

    bool need_fallback = (total > CAP);
    int  wrote = 0;
    const float binscale = (float)NBIN / (1.0f - T0);

    if (!need_fallback) {
        // ---- ONE gmem sweep: stage candidates in smem + histogram ---------
        hist[tid] = 0;
        __syncthreads();
        for (int i = tid; i < C; i += NTN) {
            float s = g_cand_s[b * CAP + i];
            ts[i] = s;
            tp[i] = g_cand_i[b * CAP + i];
            int bin = min(NBIN - 1, max(0, (int)((s - T0) * binscale)));
            atomicAdd(&hist[bin], 1);
        }
        __syncthreads();
        // ---- suffix sum (warp shuffles); hist[t] := #scores in bins >= t --
        {
            int val = hist[tid];
#pragma unroll
            for (int off = 1; off < 32; off <<= 1) {
                int v = __shfl_down_sync(0xffffffffu, val, off);
                if (lane + off < 32) val += v;
            }
            if (lane == 0) s_part[warp] = val;
            __syncthreads();
            if (warp == 0) {
                int pv = s_part[lane];
#pragma unroll
                for (int off = 1; off < 32; off <<= 1) {
                    int v = __shfl_down_sync(0xffffffffu, pv, off);
                    if (lane + off < 32) pv += v;
                }
                int excl = __shfl_down_sync(0xffffffffu, pv, 1);
                if (lane == 31) excl = 0;
                s_part[lane] = excl;
            }
            __syncthreads();
            hist[tid] = val + s_part[warp];
            __syncthreads();
        }

        for (int attempt = 0; attempt < 2 && !wrote && !need_fallback; attempt++) {
            if (tid == 0) { s_t = 0; s_K = 0; s_ovf = 0; }
            __syncthreads();
            if (attempt == 0) {
                if (hist[tid] >= TK1 && (tid == NBIN - 1 || hist[tid + 1] < TK1))
                    s_t = tid;
            }
            __syncthreads();
            int t = s_t;
            if (attempt == 0 && t < NBIN - 1 && hist[t] > KCAP1) t = t + 1;

            // ---- compact prefix candidates (smem -> smem) -----------------
            for (int i = tid; i < C; i += NTN) {
                float s = ts[i];
                int bin = min(NBIN - 1, max(0, (int)((s - T0) * binscale)));
                if (bin >= t) {
                    int pos = atomicAdd(&s_K, 1);
                    if (pos < KCAP) {
                        cs[pos]  = s;
                        cpk[pos] = tp[i];
                    }
                }
            }
            __syncthreads();
            if (s_K > KCAP) { need_fallback = true; break; }
            int K = s_K;

            // ---- distributed rank count: thread = (candidate, 1/4 segment)
            for (int i = tid; i < K; i += NTN) srank[i] = 0;
            __syncthreads();
            {
                int Kq = (K + 3) >> 2;      // segment length
                for (int w = tid; w < K * 4; w += NTN) {
                    int i   = w >> 2;
                    int seg = w & 3;
                    float si = cs[i];
                    int   ai = cpk[i] & 0xFFFF;
                    int   j0 = seg * Kq;
                    int   j1 = min(j0 + Kq, K);
                    int   r  = 0;
                    for (int j = j0; j < j1; j++) {
                        float sj = cs[j];
                        r += (sj > si) || (sj == si && (cpk[j] & 0xFFFF) < ai);
                    }
                    if (r) atomicAdd(&srank[i], r);
                }
            }
            __syncthreads();

            // ---- scatter into sorted order + boxes ------------------------
            for (int i = tid; i < K; i += NTN) {
                int   r   = srank[i];
                int   pki = cpk[i];
                int   ai  = pki & 0xFFFF;
                ws[r]    = cs[i];
                wi[r]    = ai;
                wc[r]    = (unsigned char)(pki >> 16);
                wbox[r]  = decode_box(p, b, ai);
                wkeep[r] = 1;
            }
            __syncthreads();

            // ---- per-class compaction (sorted order preserved) ------------
            for (int c = warp; c < NCLS; c += 32) {
                int m = 0;
                for (int base = 0; base < K; base += 32) {
                    int  i  = base + lane;
                    bool pr = (i < K) && (wc[i] == (unsigned char)c);
                    unsigned mask = __ballot_sync(0xffffffffu, pr);
                    if (pr) {
                        int pos = m + __popc(mask & ((1u << lane) - 1));
                        if (pos < CLSCAP)
                            cls_list[c * CLSCAP + pos] = (unsigned short)i;
                    }
                    m += __popc(mask);
                }
                if (lane == 0) {
                    s_ccnt[c] = m;
                    if (m > CLSCAP) atomicExch(&s_ovf, 1);
                }
            }
            __syncthreads();
            if (s_ovf) { need_fallback = true; break; }

            // ---- per-class greedy (order already sorted) ------------------
            for (int c = warp; c < NCLS; c += 32) {
                int m = s_ccnt[c];
                const unsigned short* L = cls_list + c * CLSCAP;
                for (int r = 0; r < m; r++) {
                    int ir = L[r];
                    if (wkeep[ir]) {
                        float4 pb = wbox[ir];
                        for (int j = r + 1 + lane; j < m; j += 32) {
                            int ij = L[j];
                            if (wkeep[ij] && iou_(pb, wbox[ij]) > 0.6f)
                                wkeep[ij] = 0;
                        }
                    }
                    __syncwarp();
                }
            }
            __syncthreads();

            // ---- survivor ranks via ballot + chunk prefix scan ------------
            int nchunk = (K + 31) / 32;
            for (int chunk = warp; chunk < nchunk; chunk += 32) {
                int  i  = chunk * 32 + lane;
                bool kp = (i < K) && wkeep[i];
                unsigned mask = __ballot_sync(0xffffffffu, kp);
                if (lane == 0) s_chunk[chunk] = __popc(mask);
            }
            __syncthreads();
            if (warp == 0) {
                int v = (lane < nchunk) ? s_chunk[lane] : 0;
                int incl = v;
#pragma unroll
                for (int off = 1; off < 32; off <<= 1) {
                    int x = __shfl_up_sync(0xffffffffu, incl, off);
                    if (lane >= off) incl += x;
                }
                if (lane < nchunk) s_chunk[lane] = incl - v;   // exclusive
                if (lane == 31) s_S = incl;
            }
            __syncthreads();
            int S = s_S;

            if (S >= POSTK) {
                for (int chunk = warp; chunk < nchunk; chunk += 32) {
                    int  i  = chunk * 32 + lane;
                    bool kp = (i < K) && wkeep[i];
                    unsigned mask = __ballot_sync(0xffffffffu, kp);
                    if (kp) {
                        int r = s_chunk[chunk] + __popc(mask & ((1u << lane) - 1));
                        if (r < POSTK) {
                            float4 bb  = wbox[i];
                            float* det = out + ((size_t)b * POSTK + r) * 5;
                            det[0] = bb.x; det[1] = bb.y;
                            det[2] = bb.z; det[3] = bb.w;
                            det[4] = ws[i];
                            out[(size_t)BATCH * POSTK * 5 + b * POSTK + r] =
                                (float)wc[i];
                        }
                    }
                }
                wrote = 1;
            }
            __syncthreads();
        }
        if (!wrote) need_fallback = true;
    }

    if (wrote) return;

    // ---- fallback: exact block-serial greedy over all anchors -------------
    // (statistically unreachable; g_score is replay-rewritten scratch)
    {
        float* gsm = g_score + b * NTOT;
        int written = 0;
        for (int k = 0; k < POSTK; k++) {
            float bv = -1e30f; int bix = 0x7fffffff;
            for (int i = tid; i < NTOT; i += NTN) {
                float s = gsm[i];
                if (s > bv || (s == bv && i < bix)) { bv = s; bix = i; }
            }
#pragma unroll
            for (int off = 16; off; off >>= 1) {
                float ov = __shfl_down_sync(0xffffffffu, bv, off);
                int   oi = __shfl_down_sync(0xffffffffu, bix, off);
                if (ov > bv || (ov == bv && oi < bix)) { bv = ov; bix = oi; }
            }
            if (lane == 0) { s_bv[warp] = bv; s_bi[warp] = bix; }
            __syncthreads();
            if (tid == 0) {
                float fv = -1e30f; int fi = 0x7fffffff;
                for (int w2 = 0; w2 < 32; w2++) {
                    float cv = s_bv[w2]; int ci = s_bi[w2];
                    if (cv > fv || (cv == fv && ci < fi)) { fv = cv; fi = ci; }
                }
                s_pval = fv;
                if (fv > -1e29f) {
                    float4 pb = decode_box(p, b, fi);
                    s_pbox = pb;
                    s_pcls = g_cls[b * NTOT + fi];
                    float* det = out + ((size_t)b * POSTK + k) * 5;
                    det[0] = pb.x; det[1] = pb.y; det[2] = pb.z; det[3] = pb.w;
                    det[4] = fv;
                    out[(size_t)BATCH * POSTK * 5 + b * POSTK + k] =
                        (float)s_pcls;
                    gsm[fi] = -1e30f;
                }
            }
            __syncthreads();
            if (s_pval <= -1e29f) break;
            written++;
            float4 pb = s_pbox;
            int    pc = s_pcls;
            for (int i = tid; i < NTOT; i += NTN) {
                float s = gsm[i];
                if (s > -1e29f && g_cls[b * NTOT + i] == pc) {
                    if (iou_(pb, decode_box(p, b, i)) > 0.6f) gsm[i] = -1e30f;
                }
            }
            __syncthreads();
        }
        for (int k = written + tid; k < POSTK; k += NTN) {
            float* det = out + ((size_t)b * POSTK + k) * 5;
            det[0] = 0.f; det[1] = 0.f; det[2] = 0.f; det[3] = 0.f; det[4] = -1.f;
            out[(size_t)BATCH * POSTK * 5 + b * POSTK + k] = -1.f;
        }
    }
}

// ---------------------------------------------------------------------------
extern "C" void kernel_launch(void* const* d_in, const int* in_sizes, int n_in,
                              void* d_out, int out_size) {
    (void)n_in; (void)out_size;

    LevelPtrs p;
    if (in_sizes[1] == 819200) {
        for (int i = 0; i < 5; i++) {          // interleaved (cls,box,ctr)/level
            p.cls[i] = (const float*)d_in[3 * i + 0];
            p.box[i] = (const float*)d_in[3 * i + 1];
            p.ctr[i] = (const float*)d_in[3 * i + 2];
        }
    } else {
        for (int i = 0; i < 5; i++) {          // planar cls x5, box x5, ctr x5
            p.cls[i] = (const float*)d_in[i];
            p.box[i] = (const float*)d_in[5 + i];
            p.ctr[i] = (const float*)d_in[10 + i];
        }
    }

    const int smem_bytes = KCAP * 16 + CAP * 4 * 2 + NBIN * 4
                         + KCAP * 4 * 5 + NCLS * CLSCAP * 2 + KCAP * 2;
    // = 12288 + 32768 + 4096 + 15360 + 10240 + 1536 = 76,288 B
    cudaFuncSetAttribute(nms_kernel,
                         cudaFuncAttributeMaxDynamicSharedMemorySize, smem_bytes);

    dim3 dgrid((NGROUP + 255) / 256, BATCH);
    decode_kernel<<<dgrid, 256>>>(p);

    nms_kernel<<<BATCH, NTN, smem_bytes>>>(p, (float*)d_out);
}